// round 3
// baseline (speedup 1.0000x reference)
#include <cuda_runtime.h>

#define IMH 1024
#define IMW 1024
#define NPLANE (IMH*IMW)          // 1048576
#define NTENSOR (4*NPLANE)        // 4194304
#define NTOTAL  (8*NPLANE)        // 8388608
#define BIGV 1e10f

// ---- scratch (static device globals; no allocations anywhere) ----
__device__ float g_labA[NTOTAL];
__device__ float g_labB[NTOTAL];
__device__ unsigned char g_mask[NTOTAL];
__device__ unsigned int g_minmax[4];            // [img_min, img_max, lab_min, lab_max] as uint-coded nonneg floats
__device__ unsigned int g_bitmap[2][NTENSOR/32];// 2 x 524KB bit sets
__device__ int g_zeroflag[2];
__device__ int g_fgcount;

// ------------------------------------------------------------------
__global__ void k_init() {
    int i = blockIdx.x * blockDim.x + threadIdx.x;
    int total = 2 * (NTENSOR / 32);
    unsigned int* bm = &g_bitmap[0][0];
    for (int j = i; j < total; j += gridDim.x * blockDim.x) bm[j] = 0u;
    if (i == 0) {
        g_minmax[0] = 0xFFFFFFFFu; g_minmax[1] = 0u;
        g_minmax[2] = 0xFFFFFFFFu; g_minmax[3] = 0u;
        g_zeroflag[0] = 0; g_zeroflag[1] = 0;
        g_fgcount = 0;
    }
}

// ---- opening_cross (erosion then dilation, cross SE) + global min/max ----
__global__ __launch_bounds__(1024) void k_open(const float* __restrict__ img,
                                               const float* __restrict__ lab) {
    __shared__ float xs[36][37];
    __shared__ float er[34][35];
    __shared__ float smn[32], smx[32];

    int p = blockIdx.z;
    const float* src = (p < 4) ? (img + p * NPLANE) : (lab + (p - 4) * NPLANE);
    int x0 = blockIdx.x * 32, y0 = blockIdx.y * 32;
    int tx = threadIdx.x, ty = threadIdx.y;
    int tid = ty * 32 + tx;

    // load tile + 2-halo; OOB -> BIG (erosion pad)
    for (int i = tid; i < 36 * 36; i += 1024) {
        int yy = i / 36, xx = i % 36;
        int gy = y0 + yy - 2, gx = x0 + xx - 2;
        float v = BIGV;
        if ((unsigned)gy < IMH && (unsigned)gx < IMW) v = src[gy * IMW + gx];
        xs[yy][xx] = v;
    }
    __syncthreads();

    // erosion on tile + 1-halo; OOB-of-image -> -BIG (dilation pad)
    for (int i = tid; i < 34 * 34; i += 1024) {
        int yy = i / 34, xx = i % 34;
        int gy = y0 + yy - 1, gx = x0 + xx - 1;
        float e;
        if ((unsigned)gy < IMH && (unsigned)gx < IMW) {
            e = xs[yy + 1][xx + 1];
            e = fminf(e, xs[yy][xx + 1]);
            e = fminf(e, xs[yy + 2][xx + 1]);
            e = fminf(e, xs[yy + 1][xx]);
            e = fminf(e, xs[yy + 1][xx + 2]);
        } else {
            e = -BIGV;
        }
        er[yy][xx] = e;
    }
    __syncthreads();

    // dilation -> opened value, one pixel per thread
    float o = er[ty + 1][tx + 1];
    o = fmaxf(o, er[ty][tx + 1]);
    o = fmaxf(o, er[ty + 2][tx + 1]);
    o = fmaxf(o, er[ty + 1][tx]);
    o = fmaxf(o, er[ty + 1][tx + 2]);
    g_labA[p * NPLANE + (y0 + ty) * IMW + (x0 + tx)] = o;

    // block min/max reduce -> per-tensor atomics (nonneg floats: uint order == float order)
    float wm = o, wx = o;
    #pragma unroll
    for (int s = 16; s > 0; s >>= 1) {
        wm = fminf(wm, __shfl_xor_sync(0xFFFFFFFFu, wm, s));
        wx = fmaxf(wx, __shfl_xor_sync(0xFFFFFFFFu, wx, s));
    }
    int wid = tid >> 5, lane = tid & 31;
    if (lane == 0) { smn[wid] = wm; smx[wid] = wx; }
    __syncthreads();
    if (wid == 0) {
        wm = smn[lane]; wx = smx[lane];
        #pragma unroll
        for (int s = 16; s > 0; s >>= 1) {
            wm = fminf(wm, __shfl_xor_sync(0xFFFFFFFFu, wm, s));
            wx = fmaxf(wx, __shfl_xor_sync(0xFFFFFFFFu, wx, s));
        }
        if (lane == 0) {
            int t = p >> 2;
            atomicMin(&g_minmax[t * 2 + 0], __float_as_uint(wm));
            atomicMax(&g_minmax[t * 2 + 1], __float_as_uint(wx));
        }
    }
}

// ---- normalize + binarize + init labels (idx * mask) + lab fg count ----
__global__ void k_thresh() {
    __shared__ int sred[256];
    int i = blockIdx.x * 256 + threadIdx.x;
    int t = i >> 22;
    float mn = __uint_as_float(g_minmax[t * 2 + 0]);
    float mx = __uint_as_float(g_minmax[t * 2 + 1]);
    float v = g_labA[i];
    // IEEE round-to-nearest division, immune to fast-math compile flags;
    // matches XLA's div.rn.f32 lowering exactly.
    float nrm = __fdiv_rn(v - mn, mx - mn + 1e-10f);
    int m = (nrm >= 0.5f) ? 1 : 0;
    unsigned idx = (unsigned)i & (NTENSOR - 1);
    g_labA[i] = m ? (float)idx : 0.0f;
    g_mask[i] = (unsigned char)m;

    int c = (t == 1) ? m : 0;
    sred[threadIdx.x] = c;
    __syncthreads();
    for (int s = 128; s > 0; s >>= 1) {
        if (threadIdx.x < s) sred[threadIdx.x] += sred[threadIdx.x + s];
        __syncthreads();
    }
    if (threadIdx.x == 0 && sred[0]) atomicAdd(&g_fgcount, sred[0]);
}

// ---- fused k-iteration masked 3x3-max propagation ----
// tile 128x64, halo 8 -> output 112x48 per block. block (16,64)=1024 thr, 8 px/thread.
__global__ __launch_bounds__(1024, 1) void k_prop(int ab, int kIter) {
    const float* __restrict__ src = ab ? g_labB : g_labA;
    float*       __restrict__ dst = ab ? g_labA : g_labB;

    __shared__ float rmS[64][132];   // padded stride -> conflict-free float4
    __shared__ float eL[64][16];
    __shared__ float eR[64][16];

    int tx = threadIdx.x;            // 0..15
    int ty = threadIdx.y;            // 0..63
    int p  = blockIdx.z;
    int gx0 = blockIdx.x * 112 - 8;
    int gy0 = blockIdx.y * 48  - 8;
    int gy  = gy0 + ty;
    int gxb = gx0 + tx * 8;
    const float* __restrict__ sp = src + p * NPLANE;
    const unsigned char* __restrict__ mp = g_mask + p * NPLANE;

    float v[8];
    unsigned mb = 0;
    bool rowOK = ((unsigned)gy < IMH);
    if (rowOK && gxb >= 0 && gxb + 8 <= IMW) {
        const float4* q = (const float4*)(sp + gy * IMW + gxb);
        float4 a = q[0], b = q[1];
        v[0]=a.x; v[1]=a.y; v[2]=a.z; v[3]=a.w;
        v[4]=b.x; v[5]=b.y; v[6]=b.z; v[7]=b.w;
        unsigned long long M = *(const unsigned long long*)(mp + gy * IMW + gxb);
        #pragma unroll
        for (int j = 0; j < 8; j++) mb |= (((unsigned)(M >> (8 * j)) & 1u) << j);
    } else {
        #pragma unroll
        for (int j = 0; j < 8; j++) {
            int gx = gxb + j;
            bool ok = rowOK && ((unsigned)gx < IMW);
            v[j] = ok ? sp[gy * IMW + gx] : 0.0f;
            if (ok && mp[gy * IMW + gx]) mb |= (1u << j);
        }
    }

    for (int it = 0; it < kIter; ++it) {
        eL[ty][tx] = v[0];
        eR[ty][tx] = v[7];
        __syncthreads();
        float vl = (tx > 0)  ? eR[ty][tx - 1] : v[0];   // tile-edge garbage is confined to halo
        float vr = (tx < 15) ? eL[ty][tx + 1] : v[7];

        float rm[8];
        rm[0] = fmaxf(fmaxf(vl, v[0]), v[1]);
        #pragma unroll
        for (int j = 1; j < 7; j++) rm[j] = fmaxf(fmaxf(v[j - 1], v[j]), v[j + 1]);
        rm[7] = fmaxf(fmaxf(v[6], v[7]), vr);

        float* rp = &rmS[ty][tx * 8];
        ((float4*)rp)[0] = make_float4(rm[0], rm[1], rm[2], rm[3]);
        ((float4*)rp)[1] = make_float4(rm[4], rm[5], rm[6], rm[7]);
        __syncthreads();

        int yu = (ty == 0)  ? 0  : ty - 1;
        int yd = (ty == 63) ? 63 : ty + 1;
        float4 u0 = *(const float4*)&rmS[yu][tx * 8];
        float4 u1 = *(const float4*)&rmS[yu][tx * 8 + 4];
        float4 d0 = *(const float4*)&rmS[yd][tx * 8];
        float4 d1 = *(const float4*)&rmS[yd][tx * 8 + 4];

        float nv[8];
        nv[0] = fmaxf(fmaxf(u0.x, d0.x), rm[0]);
        nv[1] = fmaxf(fmaxf(u0.y, d0.y), rm[1]);
        nv[2] = fmaxf(fmaxf(u0.z, d0.z), rm[2]);
        nv[3] = fmaxf(fmaxf(u0.w, d0.w), rm[3]);
        nv[4] = fmaxf(fmaxf(u1.x, d1.x), rm[4]);
        nv[5] = fmaxf(fmaxf(u1.y, d1.y), rm[5]);
        nv[6] = fmaxf(fmaxf(u1.z, d1.z), rm[6]);
        nv[7] = fmaxf(fmaxf(u1.w, d1.w), rm[7]);
        #pragma unroll
        for (int j = 0; j < 8; j++) v[j] = ((mb >> j) & 1u) ? nv[j] : v[j];
    }

    // store valid interior (halo=8 ring dropped)
    if (ty >= 8 && ty < 56 && rowOK && tx >= 1 && tx < 15) {
        float* dp = dst + p * NPLANE + gy * IMW + gxb;
        if (gxb + 8 <= IMW) {
            ((float4*)dp)[0] = make_float4(v[0], v[1], v[2], v[3]);
            ((float4*)dp)[1] = make_float4(v[4], v[5], v[6], v[7]);
        } else {
            #pragma unroll
            for (int j = 0; j < 8; j++)
                if (gxb + j < IMW) dp[j] = v[j];
        }
    }
}

// ---- mark distinct final values: bit[int(label)] ; zero-flag for value 0 ----
__global__ void k_count() {
    int i = blockIdx.x * 256 + threadIdx.x;
    float v = g_labB[i];
    int t = i >> 22;
    if (v == 0.0f) {
        g_zeroflag[t] = 1;                       // idempotent racing store
    } else {
        float vp = __shfl_up_sync(0xFFFFFFFFu, v, 1);
        int lane = threadIdx.x & 31;
        if (lane == 0 || vp != v) {              // warp-dedupe (tensor boundary is warp-aligned)
            unsigned iv = (unsigned)v;
            atomicOr(&g_bitmap[t][iv >> 5], 1u << (iv & 31));
        }
    }
}

// ---- popcount-reduce bitmaps and emit scalar ----
__global__ void k_finish(float* out) {
    __shared__ int s0[1024], s1[1024];
    int tid = threadIdx.x;
    int c0 = 0, c1 = 0;
    for (int j = tid; j < NTENSOR / 32; j += 1024) {
        c0 += __popc(g_bitmap[0][j]);
        c1 += __popc(g_bitmap[1][j]);
    }
    s0[tid] = c0; s1[tid] = c1;
    __syncthreads();
    for (int s = 512; s > 0; s >>= 1) {
        if (tid < s) { s0[tid] += s0[tid + s]; s1[tid] += s1[tid + s]; }
        __syncthreads();
    }
    if (tid == 0) {
        float ccs  = (float)(s0[0] + g_zeroflag[0]);
        float ccsg = (float)(s1[0] + g_zeroflag[1]);
        float numSg = (float)g_fgcount;
        out[0] = fabsf(ccsg - ccs) / numSg;
    }
}

// ------------------------------------------------------------------
extern "C" void kernel_launch(void* const* d_in, const int* in_sizes, int n_in,
                              void* d_out, int out_size) {
    const float* img = (const float*)d_in[0];
    const float* lab = (const float*)d_in[1];
    float* out = (float*)d_out;

    k_init<<<256, 256>>>();

    dim3 ob(32, 32), og(32, 32, 8);
    k_open<<<og, ob>>>(img, lab);

    k_thresh<<<NTOTAL / 256, 256>>>();

    dim3 pb(16, 64), pg(10, 22, 8);
    int ab = 0;
    for (int l = 0; l < 19; ++l) {
        int kI = (l < 18) ? 8 : 6;   // 18*8 + 6 = 150 iterations exactly
        k_prop<<<pg, pb>>>(ab, kI);
        ab ^= 1;
    }
    // final labels land in g_labB (last launch was A -> B)

    k_count<<<NTOTAL / 256, 256>>>();
    k_finish<<<1, 1024>>>(out);
}

// round 6
// speedup vs baseline: 5.7347x; 5.7347x over previous
#include <cuda_runtime.h>

#define IMH 1024
#define IMW 1024
#define NPLANE (IMH*IMW)          // 1048576
#define NTENSOR (4*NPLANE)        // 4194304
#define NTOTAL  (8*NPLANE)        // 8388608
#define BIGV 1e10f
#define GATE 1e30f

// ---- scratch (static device globals; no allocations anywhere) ----
__device__ float g_labA[NTOTAL];
__device__ float g_labB[NTOTAL];
__device__ unsigned int g_minmax[4];            // [img_min, img_max, lab_min, lab_max]
__device__ unsigned int g_bitmap[2][NTENSOR/32];// 2 x 524KB bit sets
__device__ int g_zeroflag[2];
__device__ int g_fgcount;

// ------------------------------------------------------------------
__global__ void k_init() {
    int i = blockIdx.x * blockDim.x + threadIdx.x;
    int total = 2 * (NTENSOR / 32);
    unsigned int* bm = &g_bitmap[0][0];
    for (int j = i; j < total; j += gridDim.x * blockDim.x) bm[j] = 0u;
    if (i == 0) {
        g_minmax[0] = 0xFFFFFFFFu; g_minmax[1] = 0u;
        g_minmax[2] = 0xFFFFFFFFu; g_minmax[3] = 0u;
        g_zeroflag[0] = 0; g_zeroflag[1] = 0;
        g_fgcount = 0;
    }
}

// ---- opening_cross (erosion then dilation, cross SE) + global min/max ----
__global__ __launch_bounds__(1024) void k_open(const float* __restrict__ img,
                                               const float* __restrict__ lab) {
    __shared__ float xs[36][37];
    __shared__ float er[34][35];
    __shared__ float smn[32], smx[32];

    int p = blockIdx.z;
    const float* src = (p < 4) ? (img + p * NPLANE) : (lab + (p - 4) * NPLANE);
    int x0 = blockIdx.x * 32, y0 = blockIdx.y * 32;
    int tx = threadIdx.x, ty = threadIdx.y;
    int tid = ty * 32 + tx;

    for (int i = tid; i < 36 * 36; i += 1024) {
        int yy = i / 36, xx = i % 36;
        int gy = y0 + yy - 2, gx = x0 + xx - 2;
        float v = BIGV;
        if ((unsigned)gy < IMH && (unsigned)gx < IMW) v = src[gy * IMW + gx];
        xs[yy][xx] = v;
    }
    __syncthreads();

    for (int i = tid; i < 34 * 34; i += 1024) {
        int yy = i / 34, xx = i % 34;
        int gy = y0 + yy - 1, gx = x0 + xx - 1;
        float e;
        if ((unsigned)gy < IMH && (unsigned)gx < IMW) {
            e = xs[yy + 1][xx + 1];
            e = fminf(e, xs[yy][xx + 1]);
            e = fminf(e, xs[yy + 2][xx + 1]);
            e = fminf(e, xs[yy + 1][xx]);
            e = fminf(e, xs[yy + 1][xx + 2]);
        } else {
            e = -BIGV;
        }
        er[yy][xx] = e;
    }
    __syncthreads();

    float o = er[ty + 1][tx + 1];
    o = fmaxf(o, er[ty][tx + 1]);
    o = fmaxf(o, er[ty + 2][tx + 1]);
    o = fmaxf(o, er[ty + 1][tx]);
    o = fmaxf(o, er[ty + 1][tx + 2]);
    g_labA[p * NPLANE + (y0 + ty) * IMW + (x0 + tx)] = o;

    float wm = o, wx = o;
    #pragma unroll
    for (int s = 16; s > 0; s >>= 1) {
        wm = fminf(wm, __shfl_xor_sync(0xFFFFFFFFu, wm, s));
        wx = fmaxf(wx, __shfl_xor_sync(0xFFFFFFFFu, wx, s));
    }
    int wid = tid >> 5, lane = tid & 31;
    if (lane == 0) { smn[wid] = wm; smx[wid] = wx; }
    __syncthreads();
    if (wid == 0) {
        wm = smn[lane]; wx = smx[lane];
        #pragma unroll
        for (int s = 16; s > 0; s >>= 1) {
            wm = fminf(wm, __shfl_xor_sync(0xFFFFFFFFu, wm, s));
            wx = fmaxf(wx, __shfl_xor_sync(0xFFFFFFFFu, wx, s));
        }
        if (lane == 0) {
            int t = p >> 2;
            atomicMin(&g_minmax[t * 2 + 0], __float_as_uint(wm));
            atomicMax(&g_minmax[t * 2 + 1], __float_as_uint(wx));
        }
    }
}

// ---- normalize + binarize + init labels (idx+1 for fg, 0 for bg) + fg count ----
__global__ void k_thresh() {
    __shared__ int sred[256];
    int i = blockIdx.x * 256 + threadIdx.x;
    int t = i >> 22;
    float mn = __uint_as_float(g_minmax[t * 2 + 0]);
    float mx = __uint_as_float(g_minmax[t * 2 + 1]);
    float v = g_labA[i];
    float nrm = __fdiv_rn(v - mn, mx - mn + 1e-10f);   // IEEE div, matches XLA
    int m = (nrm >= 0.5f) ? 1 : 0;
    unsigned idx = (unsigned)i & (NTENSOR - 1);
    g_labA[i] = m ? (float)(idx + 1u) : 0.0f;          // shifted labels: fg > 0 always

    int c = (t == 1) ? m : 0;
    sred[threadIdx.x] = c;
    __syncthreads();
    for (int s = 128; s > 0; s >>= 1) {
        if (threadIdx.x < s) sred[threadIdx.x] += sred[threadIdx.x + s];
        __syncthreads();
    }
    if (threadIdx.x == 0 && sred[0]) atomicAdd(&g_fgcount, sred[0]);
}

// ------------------------------------------------------------------
// fused k-iteration masked 3x3-max propagation, register-blocked.
// Tile 128x128, block (16,16)=256 threads, each thread an 8x8 patch.
// Halo 8 -> interior 112x112. Shared exchange: per-thread edge cols + top/bot rows.
// Mask is implicit: bg px are exactly 0 forever; gate = fmin(nv, v*1e30).
// Monotone labels -> early exit when a full iteration changes nothing.
// Slot layout: 8 floats/thread, +4-float pad per 4-thread group (no overlap,
// 16B-aligned, 2-way bank conflicts on float4).
__device__ __forceinline__ int sbase(int ty, int tx) {
    int tid = (ty << 4) + tx;
    return (tid << 3) + ((tid >> 2) << 2);
}
__device__ __forceinline__ void hmax8(const float* s, float L, float R, float* o) {
    o[0] = fmaxf(fmaxf(L, s[0]), s[1]);
    #pragma unroll
    for (int j = 1; j < 7; j++) o[j] = fmaxf(fmaxf(s[j - 1], s[j]), s[j + 1]);
    o[7] = fmaxf(fmaxf(s[6], s[7]), R);
}

#define SXN 2304   // 255*8 + 63*4 + 8 = 2300 -> round up

__global__ __launch_bounds__(256, 2) void k_prop(int ab, int kIter) {
    const float* __restrict__ src = ab ? g_labB : g_labA;
    float*       __restrict__ dst = ab ? g_labA : g_labB;

    __shared__ float sEL[SXN];   // per-thread left-edge column (8 rows)
    __shared__ float sER[SXN];   // right-edge column
    __shared__ float sTV[SXN];   // top row (8 cols)
    __shared__ float sBV[SXN];   // bottom row

    int tx = threadIdx.x;         // 0..15
    int ty = threadIdx.y;         // 0..15
    int p  = blockIdx.z;
    int gx0 = blockIdx.x * 112 - 8;
    int gy0 = blockIdx.y * 112 - 8;
    int gxb = gx0 + tx * 8;
    const float* __restrict__ sp = src + p * NPLANE;

    float v[8][8];
    bool colOK = ((unsigned)gxb < IMW);   // segments are 8-aligned: all-or-nothing
    #pragma unroll
    for (int r = 0; r < 8; r++) {
        int gy = gy0 + ty * 8 + r;
        if (colOK && (unsigned)gy < IMH) {
            float4 a = *(const float4*)(sp + gy * IMW + gxb);
            float4 b = *(const float4*)(sp + gy * IMW + gxb + 4);
            v[r][0]=a.x; v[r][1]=a.y; v[r][2]=a.z; v[r][3]=a.w;
            v[r][4]=b.x; v[r][5]=b.y; v[r][6]=b.z; v[r][7]=b.w;
        } else {
            #pragma unroll
            for (int j = 0; j < 8; j++) v[r][j] = 0.0f;
        }
    }

    int base = sbase(ty, tx);
    bool changed = false;

    for (int it = 0; it < kIter; ++it) {
        if (it > 0) {
            if (!__syncthreads_or((int)changed)) break;   // converged: rest are no-ops
            changed = false;
        }
        // ---- write exchange data ----
        *(float4*)&sEL[base]     = make_float4(v[0][0], v[1][0], v[2][0], v[3][0]);
        *(float4*)&sEL[base + 4] = make_float4(v[4][0], v[5][0], v[6][0], v[7][0]);
        *(float4*)&sER[base]     = make_float4(v[0][7], v[1][7], v[2][7], v[3][7]);
        *(float4*)&sER[base + 4] = make_float4(v[4][7], v[5][7], v[6][7], v[7][7]);
        *(float4*)&sTV[base]     = make_float4(v[0][0], v[0][1], v[0][2], v[0][3]);
        *(float4*)&sTV[base + 4] = make_float4(v[0][4], v[0][5], v[0][6], v[0][7]);
        *(float4*)&sBV[base]     = make_float4(v[7][0], v[7][1], v[7][2], v[7][3]);
        *(float4*)&sBV[base + 4] = make_float4(v[7][4], v[7][5], v[7][6], v[7][7]);
        __syncthreads();

        // ---- read neighbors (tile-edge threads are pure halo; 0 is safe) ----
        float vl[8], vr[8], up[8], dn[8];
        float upL = 0.f, upR = 0.f, dnL = 0.f, dnR = 0.f;
        if (tx > 0) {
            int b = sbase(ty, tx - 1);
            float4 a = *(const float4*)&sER[b], c = *(const float4*)&sER[b + 4];
            vl[0]=a.x; vl[1]=a.y; vl[2]=a.z; vl[3]=a.w; vl[4]=c.x; vl[5]=c.y; vl[6]=c.z; vl[7]=c.w;
        } else {
            #pragma unroll
            for (int r = 0; r < 8; r++) vl[r] = 0.f;
        }
        if (tx < 15) {
            int b = sbase(ty, tx + 1);
            float4 a = *(const float4*)&sEL[b], c = *(const float4*)&sEL[b + 4];
            vr[0]=a.x; vr[1]=a.y; vr[2]=a.z; vr[3]=a.w; vr[4]=c.x; vr[5]=c.y; vr[6]=c.z; vr[7]=c.w;
        } else {
            #pragma unroll
            for (int r = 0; r < 8; r++) vr[r] = 0.f;
        }
        if (ty > 0) {
            int b = sbase(ty - 1, tx);
            float4 a = *(const float4*)&sBV[b], c = *(const float4*)&sBV[b + 4];
            up[0]=a.x; up[1]=a.y; up[2]=a.z; up[3]=a.w; up[4]=c.x; up[5]=c.y; up[6]=c.z; up[7]=c.w;
            if (tx > 0)  upL = sER[sbase(ty - 1, tx - 1) + 7];
            if (tx < 15) upR = sEL[sbase(ty - 1, tx + 1) + 7];
        } else {
            #pragma unroll
            for (int j = 0; j < 8; j++) up[j] = 0.f;
        }
        if (ty < 15) {
            int b = sbase(ty + 1, tx);
            float4 a = *(const float4*)&sTV[b], c = *(const float4*)&sTV[b + 4];
            dn[0]=a.x; dn[1]=a.y; dn[2]=a.z; dn[3]=a.w; dn[4]=c.x; dn[5]=c.y; dn[6]=c.z; dn[7]=c.w;
            if (tx > 0)  dnL = sER[sbase(ty + 1, tx - 1) + 0];
            if (tx < 15) dnR = sEL[sbase(ty + 1, tx + 1) + 0];
        } else {
            #pragma unroll
            for (int j = 0; j < 8; j++) dn[j] = 0.f;
        }

        // ---- rolling 3-row vertical combine over horizontal maxes (Jacobi) ----
        float rm[3][8];
        hmax8(up,   upL,   upR,   rm[0]);     // row -1
        hmax8(v[0], vl[0], vr[0], rm[1]);     // row 0
        #pragma unroll
        for (int r = 0; r < 8; r++) {
            float* rmN = rm[(r + 2) % 3];
            if (r < 7) hmax8(v[r + 1], vl[r + 1], vr[r + 1], rmN);
            else       hmax8(dn, dnL, dnR, rmN);
            float* rmP = rm[r % 3];
            float* rmC = rm[(r + 1) % 3];
            #pragma unroll
            for (int j = 0; j < 8; j++) {
                float nv = fmaxf(fmaxf(rmP[j], rmC[j]), rmN[j]);
                nv = fminf(nv, v[r][j] * GATE);          // bg (0) stays 0, fg takes nv
                changed = changed || (nv != v[r][j]);
                v[r][j] = nv;
            }
        }
    }

    // ---- store interior (8-ring halo dropped; 8-aligned segments) ----
    if (tx >= 1 && tx <= 14 && ty >= 1 && ty <= 14 && (unsigned)gxb < IMW) {
        float* __restrict__ dp = dst + p * NPLANE;
        #pragma unroll
        for (int r = 0; r < 8; r++) {
            int gy = gy0 + ty * 8 + r;
            if ((unsigned)gy < IMH) {
                *(float4*)(dp + gy * IMW + gxb)     = make_float4(v[r][0], v[r][1], v[r][2], v[r][3]);
                *(float4*)(dp + gy * IMW + gxb + 4) = make_float4(v[r][4], v[r][5], v[r][6], v[r][7]);
            }
        }
    }
}

// ---- mark distinct final values: bit[int(label)-1]; zero-flag for 0 ----
__global__ void k_count() {
    int i = blockIdx.x * 256 + threadIdx.x;
    float v = g_labB[i];
    int t = i >> 22;
    if (v == 0.0f) {
        g_zeroflag[t] = 1;
    } else {
        float vp = __shfl_up_sync(0xFFFFFFFFu, v, 1);
        int lane = threadIdx.x & 31;
        if (lane == 0 || vp != v) {
            unsigned iv = (unsigned)v - 1u;
            atomicOr(&g_bitmap[t][iv >> 5], 1u << (iv & 31));
        }
    }
}

// ---- popcount-reduce bitmaps and emit scalar ----
__global__ void k_finish(float* out) {
    __shared__ int s0[1024], s1[1024];
    int tid = threadIdx.x;
    int c0 = 0, c1 = 0;
    for (int j = tid; j < NTENSOR / 32; j += 1024) {
        c0 += __popc(g_bitmap[0][j]);
        c1 += __popc(g_bitmap[1][j]);
    }
    s0[tid] = c0; s1[tid] = c1;
    __syncthreads();
    for (int s = 512; s > 0; s >>= 1) {
        if (tid < s) { s0[tid] += s0[tid + s]; s1[tid] += s1[tid + s]; }
        __syncthreads();
    }
    if (tid == 0) {
        float ccs  = (float)(s0[0] + g_zeroflag[0]);
        float ccsg = (float)(s1[0] + g_zeroflag[1]);
        float numSg = (float)g_fgcount;
        out[0] = fabsf(ccsg - ccs) / numSg;
    }
}

// ------------------------------------------------------------------
extern "C" void kernel_launch(void* const* d_in, const int* in_sizes, int n_in,
                              void* d_out, int out_size) {
    const float* img = (const float*)d_in[0];
    const float* lab = (const float*)d_in[1];
    float* out = (float*)d_out;

    k_init<<<256, 256>>>();

    dim3 ob(32, 32), og(32, 32, 8);
    k_open<<<og, ob>>>(img, lab);

    k_thresh<<<NTOTAL / 256, 256>>>();

    dim3 pb(16, 16), pg(10, 10, 8);
    int ab = 0;
    for (int l = 0; l < 19; ++l) {
        int kI = (l < 18) ? 8 : 6;   // 18*8 + 6 = 150 iterations exactly
        k_prop<<<pg, pb>>>(ab, kI);
        ab ^= 1;
    }
    // final labels land in g_labB

    k_count<<<NTOTAL / 256, 256>>>();
    k_finish<<<1, 1024>>>(out);
}

// round 7
// speedup vs baseline: 8.8298x; 1.5397x over previous
#include <cuda_runtime.h>

#define IMH 1024
#define IMW 1024
#define NPLANE (IMH*IMW)          // 1048576
#define NTENSOR (4*NPLANE)        // 4194304
#define NTOTAL  (8*NPLANE)        // 8388608
#define BIGV 1e10f
#define GATE 1e30f
#define NBLK_PROP 800             // 10*10*8

// ---- scratch (static device globals; no allocations anywhere) ----
__device__ float g_labA[NTOTAL];
__device__ float g_labB[NTOTAL];
__device__ unsigned int g_minmax[4];            // [img_min, img_max, lab_min, lab_max]
__device__ unsigned int g_bitmap[2][NTENSOR/32];// 2 x 524KB bit sets
__device__ int g_zeroflag[2];
__device__ int g_fgcount;
__device__ int g_cc[2];
// convergence control
__device__ int g_done;
__device__ int g_anyChange;
__device__ int g_blkDone;
__device__ int g_cur;            // 0 = g_labA holds final data, 1 = g_labB

// ------------------------------------------------------------------
__global__ void k_init() {
    int i = blockIdx.x * blockDim.x + threadIdx.x;
    int total = 2 * (NTENSOR / 32);
    unsigned int* bm = &g_bitmap[0][0];
    for (int j = i; j < total; j += gridDim.x * blockDim.x) bm[j] = 0u;
    if (i == 0) {
        g_minmax[0] = 0xFFFFFFFFu; g_minmax[1] = 0u;
        g_minmax[2] = 0xFFFFFFFFu; g_minmax[3] = 0u;
        g_zeroflag[0] = 0; g_zeroflag[1] = 0;
        g_fgcount = 0;
        g_cc[0] = 0; g_cc[1] = 0;
        g_done = 0; g_anyChange = 0; g_blkDone = 0; g_cur = 1;
    }
}

// ---- opening_cross (erosion then dilation, cross SE) + global min/max ----
__global__ __launch_bounds__(1024) void k_open(const float* __restrict__ img,
                                               const float* __restrict__ lab) {
    __shared__ float xs[36][37];
    __shared__ float er[34][35];
    __shared__ float smn[32], smx[32];

    int p = blockIdx.z;
    const float* src = (p < 4) ? (img + p * NPLANE) : (lab + (p - 4) * NPLANE);
    int x0 = blockIdx.x * 32, y0 = blockIdx.y * 32;
    int tx = threadIdx.x, ty = threadIdx.y;
    int tid = ty * 32 + tx;

    for (int i = tid; i < 36 * 36; i += 1024) {
        int yy = i / 36, xx = i % 36;
        int gy = y0 + yy - 2, gx = x0 + xx - 2;
        float v = BIGV;
        if ((unsigned)gy < IMH && (unsigned)gx < IMW) v = src[gy * IMW + gx];
        xs[yy][xx] = v;
    }
    __syncthreads();

    for (int i = tid; i < 34 * 34; i += 1024) {
        int yy = i / 34, xx = i % 34;
        int gy = y0 + yy - 1, gx = x0 + xx - 1;
        float e;
        if ((unsigned)gy < IMH && (unsigned)gx < IMW) {
            e = xs[yy + 1][xx + 1];
            e = fminf(e, xs[yy][xx + 1]);
            e = fminf(e, xs[yy + 2][xx + 1]);
            e = fminf(e, xs[yy + 1][xx]);
            e = fminf(e, xs[yy + 1][xx + 2]);
        } else {
            e = -BIGV;
        }
        er[yy][xx] = e;
    }
    __syncthreads();

    float o = er[ty + 1][tx + 1];
    o = fmaxf(o, er[ty][tx + 1]);
    o = fmaxf(o, er[ty + 2][tx + 1]);
    o = fmaxf(o, er[ty + 1][tx]);
    o = fmaxf(o, er[ty + 1][tx + 2]);
    g_labA[p * NPLANE + (y0 + ty) * IMW + (x0 + tx)] = o;

    float wm = o, wx = o;
    #pragma unroll
    for (int s = 16; s > 0; s >>= 1) {
        wm = fminf(wm, __shfl_xor_sync(0xFFFFFFFFu, wm, s));
        wx = fmaxf(wx, __shfl_xor_sync(0xFFFFFFFFu, wx, s));
    }
    int wid = tid >> 5, lane = tid & 31;
    if (lane == 0) { smn[wid] = wm; smx[wid] = wx; }
    __syncthreads();
    if (wid == 0) {
        wm = smn[lane]; wx = smx[lane];
        #pragma unroll
        for (int s = 16; s > 0; s >>= 1) {
            wm = fminf(wm, __shfl_xor_sync(0xFFFFFFFFu, wm, s));
            wx = fmaxf(wx, __shfl_xor_sync(0xFFFFFFFFu, wx, s));
        }
        if (lane == 0) {
            int t = p >> 2;
            atomicMin(&g_minmax[t * 2 + 0], __float_as_uint(wm));
            atomicMax(&g_minmax[t * 2 + 1], __float_as_uint(wx));
        }
    }
}

// ---- normalize + binarize + init labels (idx+1 for fg, 0 for bg) + fg count ----
__global__ void k_thresh() {
    __shared__ int sred[256];
    int i = blockIdx.x * 256 + threadIdx.x;
    int t = i >> 22;
    float mn = __uint_as_float(g_minmax[t * 2 + 0]);
    float mx = __uint_as_float(g_minmax[t * 2 + 1]);
    float v = g_labA[i];
    float nrm = __fdiv_rn(v - mn, mx - mn + 1e-10f);   // IEEE div, matches XLA
    int m = (nrm >= 0.5f) ? 1 : 0;
    unsigned idx = (unsigned)i & (NTENSOR - 1);
    g_labA[i] = m ? (float)(idx + 1u) : 0.0f;          // shifted labels: fg > 0 always

    int c = (t == 1) ? m : 0;
    sred[threadIdx.x] = c;
    __syncthreads();
    for (int s = 128; s > 0; s >>= 1) {
        if (threadIdx.x < s) sred[threadIdx.x] += sred[threadIdx.x + s];
        __syncthreads();
    }
    if (threadIdx.x == 0 && sred[0]) atomicAdd(&g_fgcount, sred[0]);
}

// ------------------------------------------------------------------
// fused k-iteration masked 3x3-max propagation, register-blocked.
// Tile 128x128, block (16,16)=256 threads, each thread an 8x8 patch.
// Halo 8 -> interior 112x112. Mask implicit: bg px are exactly 0 forever.
// Block-level early exit + launch-level global convergence skip.
__device__ __forceinline__ int sbase(int ty, int tx) {
    int tid = (ty << 4) + tx;
    return (tid << 3) + ((tid >> 2) << 2);   // 8 floats + 4 pad per 4-thread group
}
__device__ __forceinline__ void hmax8(const float* s, float L, float R, float* o) {
    o[0] = fmaxf(fmaxf(L, s[0]), s[1]);
    #pragma unroll
    for (int j = 1; j < 7; j++) o[j] = fmaxf(fmaxf(s[j - 1], s[j]), s[j + 1]);
    o[7] = fmaxf(fmaxf(s[6], s[7]), R);
}

#define SXN 2304

__global__ __launch_bounds__(256, 2) void k_prop(int ab, int kIter) {
    if (g_done) return;                       // globally converged: launch is a no-op

    const float* __restrict__ src = ab ? g_labB : g_labA;
    float*       __restrict__ dst = ab ? g_labA : g_labB;

    __shared__ float sEL[SXN];
    __shared__ float sER[SXN];
    __shared__ float sTV[SXN];
    __shared__ float sBV[SXN];

    int tx = threadIdx.x;         // 0..15
    int ty = threadIdx.y;         // 0..15
    int p  = blockIdx.z;
    int gx0 = blockIdx.x * 112 - 8;
    int gy0 = blockIdx.y * 112 - 8;
    int gxb = gx0 + tx * 8;
    const float* __restrict__ sp = src + p * NPLANE;

    float v[8][8];
    bool colOK = ((unsigned)gxb < IMW);
    #pragma unroll
    for (int r = 0; r < 8; r++) {
        int gy = gy0 + ty * 8 + r;
        if (colOK && (unsigned)gy < IMH) {
            float4 a = *(const float4*)(sp + gy * IMW + gxb);
            float4 b = *(const float4*)(sp + gy * IMW + gxb + 4);
            v[r][0]=a.x; v[r][1]=a.y; v[r][2]=a.z; v[r][3]=a.w;
            v[r][4]=b.x; v[r][5]=b.y; v[r][6]=b.z; v[r][7]=b.w;
        } else {
            #pragma unroll
            for (int j = 0; j < 8; j++) v[r][j] = 0.0f;
        }
    }

    int base = sbase(ty, tx);
    bool changed = false;
    bool tchanged = false;

    for (int it = 0; it < kIter; ++it) {
        if (it > 0) {
            if (!__syncthreads_or((int)changed)) break;
            changed = false;
        }
        *(float4*)&sEL[base]     = make_float4(v[0][0], v[1][0], v[2][0], v[3][0]);
        *(float4*)&sEL[base + 4] = make_float4(v[4][0], v[5][0], v[6][0], v[7][0]);
        *(float4*)&sER[base]     = make_float4(v[0][7], v[1][7], v[2][7], v[3][7]);
        *(float4*)&sER[base + 4] = make_float4(v[4][7], v[5][7], v[6][7], v[7][7]);
        *(float4*)&sTV[base]     = make_float4(v[0][0], v[0][1], v[0][2], v[0][3]);
        *(float4*)&sTV[base + 4] = make_float4(v[0][4], v[0][5], v[0][6], v[0][7]);
        *(float4*)&sBV[base]     = make_float4(v[7][0], v[7][1], v[7][2], v[7][3]);
        *(float4*)&sBV[base + 4] = make_float4(v[7][4], v[7][5], v[7][6], v[7][7]);
        __syncthreads();

        float vl[8], vr[8], up[8], dn[8];
        float upL = 0.f, upR = 0.f, dnL = 0.f, dnR = 0.f;
        if (tx > 0) {
            int b = sbase(ty, tx - 1);
            float4 a = *(const float4*)&sER[b], c = *(const float4*)&sER[b + 4];
            vl[0]=a.x; vl[1]=a.y; vl[2]=a.z; vl[3]=a.w; vl[4]=c.x; vl[5]=c.y; vl[6]=c.z; vl[7]=c.w;
        } else {
            #pragma unroll
            for (int r = 0; r < 8; r++) vl[r] = 0.f;
        }
        if (tx < 15) {
            int b = sbase(ty, tx + 1);
            float4 a = *(const float4*)&sEL[b], c = *(const float4*)&sEL[b + 4];
            vr[0]=a.x; vr[1]=a.y; vr[2]=a.z; vr[3]=a.w; vr[4]=c.x; vr[5]=c.y; vr[6]=c.z; vr[7]=c.w;
        } else {
            #pragma unroll
            for (int r = 0; r < 8; r++) vr[r] = 0.f;
        }
        if (ty > 0) {
            int b = sbase(ty - 1, tx);
            float4 a = *(const float4*)&sBV[b], c = *(const float4*)&sBV[b + 4];
            up[0]=a.x; up[1]=a.y; up[2]=a.z; up[3]=a.w; up[4]=c.x; up[5]=c.y; up[6]=c.z; up[7]=c.w;
            if (tx > 0)  upL = sER[sbase(ty - 1, tx - 1) + 7];
            if (tx < 15) upR = sEL[sbase(ty - 1, tx + 1) + 7];
        } else {
            #pragma unroll
            for (int j = 0; j < 8; j++) up[j] = 0.f;
        }
        if (ty < 15) {
            int b = sbase(ty + 1, tx);
            float4 a = *(const float4*)&sTV[b], c = *(const float4*)&sTV[b + 4];
            dn[0]=a.x; dn[1]=a.y; dn[2]=a.z; dn[3]=a.w; dn[4]=c.x; dn[5]=c.y; dn[6]=c.z; dn[7]=c.w;
            if (tx > 0)  dnL = sER[sbase(ty + 1, tx - 1) + 0];
            if (tx < 15) dnR = sEL[sbase(ty + 1, tx + 1) + 0];
        } else {
            #pragma unroll
            for (int j = 0; j < 8; j++) dn[j] = 0.f;
        }

        // rolling 3-row vertical combine over horizontal maxes (Jacobi)
        float rm[3][8];
        float dsum = 0.0f;                      // change detector on fma pipe
        hmax8(up,   upL,   upR,   rm[0]);
        hmax8(v[0], vl[0], vr[0], rm[1]);
        #pragma unroll
        for (int r = 0; r < 8; r++) {
            float* rmN = rm[(r + 2) % 3];
            if (r < 7) hmax8(v[r + 1], vl[r + 1], vr[r + 1], rmN);
            else       hmax8(dn, dnL, dnR, rmN);
            float* rmP = rm[r % 3];
            float* rmC = rm[(r + 1) % 3];
            #pragma unroll
            for (int j = 0; j < 8; j++) {
                float nv = fmaxf(fmaxf(rmP[j], rmC[j]), rmN[j]);
                nv = fminf(nv, v[r][j] * GATE);  // bg (0) stays 0, fg takes nv
                dsum += nv - v[r][j];            // nv >= v, exact (integer-valued floats)
                v[r][j] = nv;
            }
        }
        changed = (dsum > 0.0f);
        tchanged = tchanged || changed;
    }

    // store interior (8-ring halo dropped; 8-aligned segments)
    if (tx >= 1 && tx <= 14 && ty >= 1 && ty <= 14 && (unsigned)gxb < IMW) {
        float* __restrict__ dp = dst + p * NPLANE;
        #pragma unroll
        for (int r = 0; r < 8; r++) {
            int gy = gy0 + ty * 8 + r;
            if ((unsigned)gy < IMH) {
                *(float4*)(dp + gy * IMW + gxb)     = make_float4(v[r][0], v[r][1], v[r][2], v[r][3]);
                *(float4*)(dp + gy * IMW + gxb + 4) = make_float4(v[r][4], v[r][5], v[r][6], v[r][7]);
            }
        }
    }

    // launch-wide convergence bookkeeping (last-block pattern)
    int bc = __syncthreads_or((int)tchanged);
    if (tx == 0 && ty == 0) {
        if (bc) atomicOr(&g_anyChange, 1);
        __threadfence();
        int n = atomicAdd(&g_blkDone, 1);
        if (n == NBLK_PROP - 1) {
            g_blkDone = 0;
            int any = atomicAdd(&g_anyChange, 0);   // L2-coherent read
            if (!any) g_done = 1;
            g_anyChange = 0;
            g_cur = ab ^ 1;                          // buffer this launch wrote
        }
    }
}

// ---- mark distinct final values: bit[int(label)-1]; zero-flag for 0 ----
__global__ void k_count() {
    const float* __restrict__ src = g_cur ? g_labB : g_labA;
    int i = blockIdx.x * 256 + threadIdx.x;
    float v = src[i];
    int t = i >> 22;
    if (v == 0.0f) {
        g_zeroflag[t] = 1;
    } else {
        float vp = __shfl_up_sync(0xFFFFFFFFu, v, 1);
        int lane = threadIdx.x & 31;
        if (lane == 0 || vp != v) {
            unsigned iv = (unsigned)v - 1u;
            atomicOr(&g_bitmap[t][iv >> 5], 1u << (iv & 31));
        }
    }
}

// ---- parallel popcount partial reduction ----
__global__ void k_fin1() {
    __shared__ int s0[256], s1[256];
    int tid = threadIdx.x;
    int c0 = 0, c1 = 0;
    for (int j = blockIdx.x * 256 + tid; j < NTENSOR / 32; j += gridDim.x * 256) {
        c0 += __popc(g_bitmap[0][j]);
        c1 += __popc(g_bitmap[1][j]);
    }
    s0[tid] = c0; s1[tid] = c1;
    __syncthreads();
    for (int s = 128; s > 0; s >>= 1) {
        if (tid < s) { s0[tid] += s0[tid + s]; s1[tid] += s1[tid + s]; }
        __syncthreads();
    }
    if (tid == 0) {
        if (s0[0]) atomicAdd(&g_cc[0], s0[0]);
        if (s1[0]) atomicAdd(&g_cc[1], s1[0]);
    }
}

// ---- emit scalar ----
__global__ void k_fin2(float* out) {
    float ccs  = (float)(g_cc[0] + g_zeroflag[0]);
    float ccsg = (float)(g_cc[1] + g_zeroflag[1]);
    float numSg = (float)g_fgcount;
    out[0] = fabsf(ccsg - ccs) / numSg;
}

// ------------------------------------------------------------------
extern "C" void kernel_launch(void* const* d_in, const int* in_sizes, int n_in,
                              void* d_out, int out_size) {
    const float* img = (const float*)d_in[0];
    const float* lab = (const float*)d_in[1];
    float* out = (float*)d_out;

    k_init<<<256, 256>>>();

    dim3 ob(32, 32), og(32, 32, 8);
    k_open<<<og, ob>>>(img, lab);

    k_thresh<<<NTOTAL / 256, 256>>>();

    dim3 pb(16, 16), pg(10, 10, 8);
    int ab = 0;
    for (int l = 0; l < 19; ++l) {
        int kI = (l < 18) ? 8 : 6;   // 18*8 + 6 = 150 iterations exactly
        k_prop<<<pg, pb>>>(ab, kI);
        ab ^= 1;
    }

    k_count<<<NTOTAL / 256, 256>>>();
    k_fin1<<<256, 256>>>();
    k_fin2<<<1, 1>>>(out);
}

// round 9
// speedup vs baseline: 9.0446x; 1.0243x over previous
#include <cuda_runtime.h>

#define IMH 1024
#define IMW 1024
#define NPLANE (IMH*IMW)          // 1048576
#define NTENSOR (4*NPLANE)        // 4194304
#define NTOTAL  (8*NPLANE)        // 8388608
#define BIGV 1e10f
#define GATE 1e30f

// ---- scratch (static device globals; no allocations anywhere) ----
__device__ float g_labA[NTOTAL];
__device__ float g_labB[NTOTAL];
__device__ unsigned int g_minmax[4];            // [img_min, img_max, lab_min, lab_max]
__device__ unsigned int g_bitmap[2][NTENSOR/32];// 2 x 524KB bit sets
__device__ int g_zeroflag[2];
__device__ int g_fgcount;
__device__ int g_cc[2];
// per-tile activity flags, ping-ponged by launch parity. [par][z][by+1][bx+1], 1-ring pad = 0.
__device__ unsigned char g_flag[2][8][12][12];

// ------------------------------------------------------------------
__global__ void k_init() {
    int i = blockIdx.x * blockDim.x + threadIdx.x;
    int total = 2 * (NTENSOR / 32);
    unsigned int* bm = &g_bitmap[0][0];
    for (int j = i; j < total; j += gridDim.x * blockDim.x) bm[j] = 0u;
    // flags: parity 0 interior = 1 (launch 0 runs everything), rest = 0
    if (i < 2 * 8 * 12 * 12) {
        int par = i / 1152, rem = i % 1152;
        int z = rem / 144, yy = (rem % 144) / 12, xx = rem % 12;
        unsigned char val = (par == 0 && yy >= 1 && yy <= 10 && xx >= 1 && xx <= 10) ? 1 : 0;
        g_flag[par][z][yy][xx] = val;
    }
    if (i == 0) {
        g_minmax[0] = 0xFFFFFFFFu; g_minmax[1] = 0u;
        g_minmax[2] = 0xFFFFFFFFu; g_minmax[3] = 0u;
        g_zeroflag[0] = 0; g_zeroflag[1] = 0;
        g_fgcount = 0;
        g_cc[0] = 0; g_cc[1] = 0;
    }
}

// ---- opening_cross (erosion then dilation, cross SE) + global min/max ----
__global__ __launch_bounds__(1024) void k_open(const float* __restrict__ img,
                                               const float* __restrict__ lab) {
    __shared__ float xs[36][37];
    __shared__ float er[34][35];
    __shared__ float smn[32], smx[32];

    int p = blockIdx.z;
    const float* src = (p < 4) ? (img + p * NPLANE) : (lab + (p - 4) * NPLANE);
    int x0 = blockIdx.x * 32, y0 = blockIdx.y * 32;
    int tx = threadIdx.x, ty = threadIdx.y;
    int tid = ty * 32 + tx;

    for (int i = tid; i < 36 * 36; i += 1024) {
        int yy = i / 36, xx = i % 36;
        int gy = y0 + yy - 2, gx = x0 + xx - 2;
        float v = BIGV;
        if ((unsigned)gy < IMH && (unsigned)gx < IMW) v = src[gy * IMW + gx];
        xs[yy][xx] = v;
    }
    __syncthreads();

    for (int i = tid; i < 34 * 34; i += 1024) {
        int yy = i / 34, xx = i % 34;
        int gy = y0 + yy - 1, gx = x0 + xx - 1;
        float e;
        if ((unsigned)gy < IMH && (unsigned)gx < IMW) {
            e = xs[yy + 1][xx + 1];
            e = fminf(e, xs[yy][xx + 1]);
            e = fminf(e, xs[yy + 2][xx + 1]);
            e = fminf(e, xs[yy + 1][xx]);
            e = fminf(e, xs[yy + 1][xx + 2]);
        } else {
            e = -BIGV;
        }
        er[yy][xx] = e;
    }
    __syncthreads();

    float o = er[ty + 1][tx + 1];
    o = fmaxf(o, er[ty][tx + 1]);
    o = fmaxf(o, er[ty + 2][tx + 1]);
    o = fmaxf(o, er[ty + 1][tx]);
    o = fmaxf(o, er[ty + 1][tx + 2]);
    g_labA[p * NPLANE + (y0 + ty) * IMW + (x0 + tx)] = o;

    float wm = o, wx = o;
    #pragma unroll
    for (int s = 16; s > 0; s >>= 1) {
        wm = fminf(wm, __shfl_xor_sync(0xFFFFFFFFu, wm, s));
        wx = fmaxf(wx, __shfl_xor_sync(0xFFFFFFFFu, wx, s));
    }
    int wid = tid >> 5, lane = tid & 31;
    if (lane == 0) { smn[wid] = wm; smx[wid] = wx; }
    __syncthreads();
    if (wid == 0) {
        wm = smn[lane]; wx = smx[lane];
        #pragma unroll
        for (int s = 16; s > 0; s >>= 1) {
            wm = fminf(wm, __shfl_xor_sync(0xFFFFFFFFu, wm, s));
            wx = fmaxf(wx, __shfl_xor_sync(0xFFFFFFFFu, wx, s));
        }
        if (lane == 0) {
            int t = p >> 2;
            atomicMin(&g_minmax[t * 2 + 0], __float_as_uint(wm));
            atomicMax(&g_minmax[t * 2 + 1], __float_as_uint(wx));
        }
    }
}

// ---- normalize + binarize + init labels (idx+1 for fg, 0 for bg) + fg count ----
__global__ void k_thresh() {
    __shared__ int sred[256];
    int i = blockIdx.x * 256 + threadIdx.x;
    int t = i >> 22;
    float mn = __uint_as_float(g_minmax[t * 2 + 0]);
    float mx = __uint_as_float(g_minmax[t * 2 + 1]);
    float v = g_labA[i];
    float nrm = __fdiv_rn(v - mn, mx - mn + 1e-10f);   // IEEE div, matches XLA
    int m = (nrm >= 0.5f) ? 1 : 0;
    unsigned idx = (unsigned)i & (NTENSOR - 1);
    g_labA[i] = m ? (float)(idx + 1u) : 0.0f;          // shifted labels: fg > 0 always

    int c = (t == 1) ? m : 0;
    sred[threadIdx.x] = c;
    __syncthreads();
    for (int s = 128; s > 0; s >>= 1) {
        if (threadIdx.x < s) sred[threadIdx.x] += sred[threadIdx.x + s];
        __syncthreads();
    }
    if (threadIdx.x == 0 && sred[0]) atomicAdd(&g_fgcount, sred[0]);
}

// ------------------------------------------------------------------
// fused k-iteration masked 3x3-max propagation, register-blocked + tile skipping.
// Tile 128x128, block (16,16)=256 threads, each thread an 8x8 patch.
// Skip rule: run tile iff any 3x3-neighborhood flag (prev launch) is set.
__device__ __forceinline__ int sbase(int ty, int tx) {
    int tid = (ty << 4) + tx;
    return (tid << 3) + ((tid >> 2) << 2);   // 8 floats + 4 pad per 4-thread group
}
__device__ __forceinline__ void hmax8(const float* s, float L, float R, float* o) {
    o[0] = fmaxf(fmaxf(L, s[0]), s[1]);
    #pragma unroll
    for (int j = 1; j < 7; j++) o[j] = fmaxf(fmaxf(s[j - 1], s[j]), s[j + 1]);
    o[7] = fmaxf(fmaxf(s[6], s[7]), R);
}

#define SXN 2304

__global__ __launch_bounds__(256, 2) void k_prop(int ab, int kIter) {
    __shared__ float sEL[SXN];
    __shared__ float sER[SXN];
    __shared__ float sTV[SXN];
    __shared__ float sBV[SXN];
    __shared__ int sRun;

    int tx = threadIdx.x;         // 0..15
    int ty = threadIdx.y;         // 0..15
    int bx = blockIdx.x, by = blockIdx.y, p = blockIdx.z;

    // ---- activity gate: 3x3 neighborhood of prev-launch flags ----
    if (tx == 0 && ty == 0) {
        const unsigned char* f = &g_flag[ab][p][by][bx];  // rows by..by+2, cols bx..bx+2
        int any = 0;
        #pragma unroll
        for (int dy = 0; dy < 3; dy++)
            any |= f[dy * 12 + 0] | f[dy * 12 + 1] | f[dy * 12 + 2];
        sRun = any;
    }
    __syncthreads();
    if (!sRun) {
        if (tx == 0 && ty == 0) g_flag[ab ^ 1][p][by + 1][bx + 1] = 0;
        return;   // buffers already equal here; dst holds current values
    }

    const float* __restrict__ src = ab ? g_labB : g_labA;
    float*       __restrict__ dst = ab ? g_labA : g_labB;

    int gx0 = bx * 112 - 8;
    int gy0 = by * 112 - 8;
    int gxb = gx0 + tx * 8;
    const float* __restrict__ sp = src + p * NPLANE;

    float v[8][8];
    bool colOK = ((unsigned)gxb < IMW);
    #pragma unroll
    for (int r = 0; r < 8; r++) {
        int gy = gy0 + ty * 8 + r;
        if (colOK && (unsigned)gy < IMH) {
            float4 a = *(const float4*)(sp + gy * IMW + gxb);
            float4 b = *(const float4*)(sp + gy * IMW + gxb + 4);
            v[r][0]=a.x; v[r][1]=a.y; v[r][2]=a.z; v[r][3]=a.w;
            v[r][4]=b.x; v[r][5]=b.y; v[r][6]=b.z; v[r][7]=b.w;
        } else {
            #pragma unroll
            for (int j = 0; j < 8; j++) v[r][j] = 0.0f;
        }
    }

    int base = sbase(ty, tx);
    bool changed = false;
    bool tchanged = false;

    for (int it = 0; it < kIter; ++it) {
        if (it > 0) {
            if (!__syncthreads_or((int)changed)) break;
            changed = false;
        }
        *(float4*)&sEL[base]     = make_float4(v[0][0], v[1][0], v[2][0], v[3][0]);
        *(float4*)&sEL[base + 4] = make_float4(v[4][0], v[5][0], v[6][0], v[7][0]);
        *(float4*)&sER[base]     = make_float4(v[0][7], v[1][7], v[2][7], v[3][7]);
        *(float4*)&sER[base + 4] = make_float4(v[4][7], v[5][7], v[6][7], v[7][7]);
        *(float4*)&sTV[base]     = make_float4(v[0][0], v[0][1], v[0][2], v[0][3]);
        *(float4*)&sTV[base + 4] = make_float4(v[0][4], v[0][5], v[0][6], v[0][7]);
        *(float4*)&sBV[base]     = make_float4(v[7][0], v[7][1], v[7][2], v[7][3]);
        *(float4*)&sBV[base + 4] = make_float4(v[7][4], v[7][5], v[7][6], v[7][7]);
        __syncthreads();

        float vl[8], vr[8], up[8], dn[8];
        float upL = 0.f, upR = 0.f, dnL = 0.f, dnR = 0.f;
        if (tx > 0) {
            int b = sbase(ty, tx - 1);
            float4 a = *(const float4*)&sER[b], c = *(const float4*)&sER[b + 4];
            vl[0]=a.x; vl[1]=a.y; vl[2]=a.z; vl[3]=a.w; vl[4]=c.x; vl[5]=c.y; vl[6]=c.z; vl[7]=c.w;
        } else {
            #pragma unroll
            for (int r = 0; r < 8; r++) vl[r] = 0.f;
        }
        if (tx < 15) {
            int b = sbase(ty, tx + 1);
            float4 a = *(const float4*)&sEL[b], c = *(const float4*)&sEL[b + 4];
            vr[0]=a.x; vr[1]=a.y; vr[2]=a.z; vr[3]=a.w; vr[4]=c.x; vr[5]=c.y; vr[6]=c.z; vr[7]=c.w;
        } else {
            #pragma unroll
            for (int r = 0; r < 8; r++) vr[r] = 0.f;
        }
        if (ty > 0) {
            int b = sbase(ty - 1, tx);
            float4 a = *(const float4*)&sBV[b], c = *(const float4*)&sBV[b + 4];
            up[0]=a.x; up[1]=a.y; up[2]=a.z; up[3]=a.w; up[4]=c.x; up[5]=c.y; up[6]=c.z; up[7]=c.w;
            if (tx > 0)  upL = sER[sbase(ty - 1, tx - 1) + 7];
            if (tx < 15) upR = sEL[sbase(ty - 1, tx + 1) + 7];
        } else {
            #pragma unroll
            for (int j = 0; j < 8; j++) up[j] = 0.f;
        }
        if (ty < 15) {
            int b = sbase(ty + 1, tx);
            float4 a = *(const float4*)&sTV[b], c = *(const float4*)&sTV[b + 4];
            dn[0]=a.x; dn[1]=a.y; dn[2]=a.z; dn[3]=a.w; dn[4]=c.x; dn[5]=c.y; dn[6]=c.z; dn[7]=c.w;
            if (tx > 0)  dnL = sER[sbase(ty + 1, tx - 1) + 0];
            if (tx < 15) dnR = sEL[sbase(ty + 1, tx + 1) + 0];
        } else {
            #pragma unroll
            for (int j = 0; j < 8; j++) dn[j] = 0.f;
        }

        // rolling 3-row vertical combine over horizontal maxes (Jacobi)
        float rm[3][8];
        float dsum = 0.0f;
        hmax8(up,   upL,   upR,   rm[0]);
        hmax8(v[0], vl[0], vr[0], rm[1]);
        #pragma unroll
        for (int r = 0; r < 8; r++) {
            float* rmN = rm[(r + 2) % 3];
            if (r < 7) hmax8(v[r + 1], vl[r + 1], vr[r + 1], rmN);
            else       hmax8(dn, dnL, dnR, rmN);
            float* rmP = rm[r % 3];
            float* rmC = rm[(r + 1) % 3];
            #pragma unroll
            for (int j = 0; j < 8; j++) {
                float nv = fmaxf(fmaxf(rmP[j], rmC[j]), rmN[j]);
                nv = fminf(nv, v[r][j] * GATE);  // bg (0) stays 0, fg takes nv
                dsum += nv - v[r][j];            // nv >= v, exact (integer-valued floats)
                v[r][j] = nv;
            }
        }
        changed = (dsum > 0.0f);
        tchanged = tchanged || changed;
    }

    // store interior (8-ring halo dropped; 8-aligned segments)
    if (tx >= 1 && tx <= 14 && ty >= 1 && ty <= 14 && (unsigned)gxb < IMW) {
        float* __restrict__ dp = dst + p * NPLANE;
        #pragma unroll
        for (int r = 0; r < 8; r++) {
            int gy = gy0 + ty * 8 + r;
            if ((unsigned)gy < IMH) {
                *(float4*)(dp + gy * IMW + gxb)     = make_float4(v[r][0], v[r][1], v[r][2], v[r][3]);
                *(float4*)(dp + gy * IMW + gxb + 4) = make_float4(v[r][4], v[r][5], v[r][6], v[r][7]);
            }
        }
    }

    // publish activity flag for next launch
    int bc = __syncthreads_or((int)tchanged);
    if (tx == 0 && ty == 0) g_flag[ab ^ 1][p][by + 1][bx + 1] = bc ? 1 : 0;
}

// ---- mark distinct final values: bit[int(label)-1]; zero-flag for 0 ----
// g_labB is valid everywhere: tiles changing in the final launch were written to B;
// all other tiles have A==B (unchanged runs store values equal to their load).
__global__ void k_count() {
    int i = blockIdx.x * 256 + threadIdx.x;
    float v = g_labB[i];
    int t = i >> 22;
    if (v == 0.0f) {
        g_zeroflag[t] = 1;
    } else {
        float vp = __shfl_up_sync(0xFFFFFFFFu, v, 1);
        int lane = threadIdx.x & 31;
        if (lane == 0 || vp != v) {
            unsigned iv = (unsigned)v - 1u;
            atomicOr(&g_bitmap[t][iv >> 5], 1u << (iv & 31));
        }
    }
}

// ---- parallel popcount partial reduction ----
__global__ void k_fin1() {
    __shared__ int s0[256], s1[256];
    int tid = threadIdx.x;
    int c0 = 0, c1 = 0;
    for (int j = blockIdx.x * 256 + tid; j < NTENSOR / 32; j += gridDim.x * 256) {
        c0 += __popc(g_bitmap[0][j]);
        c1 += __popc(g_bitmap[1][j]);
    }
    s0[tid] = c0; s1[tid] = c1;
    __syncthreads();
    for (int s = 128; s > 0; s >>= 1) {
        if (tid < s) { s0[tid] += s0[tid + s]; s1[tid] += s1[tid + s]; }
        __syncthreads();
    }
    if (tid == 0) {
        if (s0[0]) atomicAdd(&g_cc[0], s0[0]);
        if (s1[0]) atomicAdd(&g_cc[1], s1[0]);
    }
}

// ---- emit scalar ----
__global__ void k_fin2(float* out) {
    float ccs  = (float)(g_cc[0] + g_zeroflag[0]);
    float ccsg = (float)(g_cc[1] + g_zeroflag[1]);
    float numSg = (float)g_fgcount;
    out[0] = fabsf(ccsg - ccs) / numSg;
}

// ------------------------------------------------------------------
extern "C" void kernel_launch(void* const* d_in, const int* in_sizes, int n_in,
                              void* d_out, int out_size) {
    const float* img = (const float*)d_in[0];
    const float* lab = (const float*)d_in[1];
    float* out = (float*)d_out;

    k_init<<<256, 256>>>();

    dim3 ob(32, 32), og(32, 32, 8);
    k_open<<<og, ob>>>(img, lab);

    k_thresh<<<NTOTAL / 256, 256>>>();

    dim3 pb(16, 16), pg(10, 10, 8);
    int ab = 0;
    for (int l = 0; l < 19; ++l) {
        int kI = (l < 18) ? 8 : 6;   // 18*8 + 6 = 150 iterations exactly
        k_prop<<<pg, pb>>>(ab, kI);
        ab ^= 1;
    }

    k_count<<<NTOTAL / 256, 256>>>();
    k_fin1<<<256, 256>>>();
    k_fin2<<<1, 1>>>(out);
}